// round 1
// baseline (speedup 1.0000x reference)
#include <cuda_runtime.h>
#include <cuda_bf16.h>

#define Cc   9
#define KSc  9
#define OUTc 16
#define NBc  16
#define Vc   20000
#define Bc   2

__global__ __launch_bounds__(128)
void nlayer_kernel(const float* __restrict__ x,
                   const float* __restrict__ W,
                   const int*   __restrict__ adj,
                   float*       __restrict__ out)
{
    __shared__ float Wsh[Cc * KSc * OUTc];   // 1296 floats = 5184 B
    for (int i = threadIdx.x; i < Cc * KSc * OUTc; i += blockDim.x)
        Wsh[i] = W[i];
    __syncthreads();

    int tid = blockIdx.x * blockDim.x + threadIdx.x;
    if (tid >= Bc * Vc) return;
    int b = tid / Vc;
    int v = tid - b * Vc;

    const float* xb = x + (size_t)b * Vc * Cc;

    // center vertex features
    float xv[Cc];
    #pragma unroll
    for (int c = 0; c < Cc; c++) xv[c] = xb[(size_t)v * Cc + c];

    // adjacency row, vectorized 4x int4
    int a[NBc];
    const int4* adj4 = reinterpret_cast<const int4*>(adj + (size_t)v * NBc);
    #pragma unroll
    for (int i = 0; i < NBc / 4; i++) {
        int4 t = __ldg(&adj4[i]);
        a[i * 4 + 0] = t.x; a[i * 4 + 1] = t.y;
        a[i * 4 + 2] = t.z; a[i * 4 + 3] = t.w;
    }

    // s[k][c] = sum_n q[n,k] * nbx[n,c]
    float s[KSc][Cc];
    #pragma unroll
    for (int k = 0; k < KSc; k++)
        #pragma unroll
        for (int c = 0; c < Cc; c++) s[k][c] = 0.0f;

    int deg = 0;

    #pragma unroll
    for (int n = 0; n < NBc; n++) {
        int an = a[n];
        int valid = (an != 0);
        deg += valid;
        int ridx = valid ? (an - 1) : 0;   // safe row; contribution masked below

        const float* nr = xb + (size_t)ridx * Cc;
        float nbv[Cc], d[Cc];
        #pragma unroll
        for (int c = 0; c < Cc; c++) {
            nbv[c] = __ldg(&nr[c]);
            d[c]   = xv[c] - nbv[c];
        }

        // softmax over the 9 channels
        float m = d[0];
        #pragma unroll
        for (int c = 1; c < Cc; c++) m = fmaxf(m, d[c]);
        float e[Cc], sum = 0.0f;
        #pragma unroll
        for (int c = 0; c < Cc; c++) { e[c] = __expf(d[c] - m); sum += e[c]; }
        float inv = __fdividef(1.0f, sum);
        float msk = valid ? inv : 0.0f;    // masking: zero neighbors contribute nothing

        #pragma unroll
        for (int k = 0; k < KSc; k++) {
            float qk = e[k] * msk;
            #pragma unroll
            for (int c = 0; c < Cc; c++)
                s[k][c] = fmaf(qk, nbv[c], s[k][c]);
        }
    }

    float invdeg = (deg > 0) ? (1.0f / (float)deg) : 0.0f;

    // out[o] = relu( invdeg * sum_{k,c} s[k,c] * W[c,k,o] )
    float acc[OUTc];
    #pragma unroll
    for (int o = 0; o < OUTc; o++) acc[o] = 0.0f;

    #pragma unroll
    for (int c = 0; c < Cc; c++) {
        #pragma unroll
        for (int k = 0; k < KSc; k++) {
            float sc = s[k][c];
            const float* wrow = &Wsh[(c * KSc + k) * OUTc];
            #pragma unroll
            for (int o = 0; o < OUTc; o++)
                acc[o] = fmaf(sc, wrow[o], acc[o]);
        }
    }

    float* op = out + (size_t)tid * OUTc;
    #pragma unroll
    for (int o = 0; o < OUTc; o++)
        op[o] = fmaxf(acc[o] * invdeg, 0.0f);
}

extern "C" void kernel_launch(void* const* d_in, const int* in_sizes, int n_in,
                              void* d_out, int out_size)
{
    const float* x   = (const float*)d_in[0];   // (2, 20000, 9)
    const float* W   = (const float*)d_in[1];   // (9, 9, 16)
    const int*   adj = (const int*)d_in[2];     // (20000, 16)
    float*       out = (float*)d_out;           // (2, 20000, 16)

    const int total   = Bc * Vc;                // 40000
    const int threads = 128;
    const int blocks  = (total + threads - 1) / threads;  // 313
    nlayer_kernel<<<blocks, threads>>>(x, W, adj, out);
}

// round 2
// speedup vs baseline: 1.0083x; 1.0083x over previous
#include <cuda_runtime.h>
#include <cuda_bf16.h>

#define Cc   9
#define KSc  9
#define OUTc 16
#define NBc  16
#define Vc   20000
#define Bc   2

__global__ __launch_bounds__(128)
void nlayer_kernel(const float* __restrict__ x,
                   const float* __restrict__ W,
                   const int*   __restrict__ adj,
                   float*       __restrict__ out)
{
    __shared__ float Wsh[Cc * KSc * OUTc];   // 1296 floats = 5184 B
    for (int i = threadIdx.x; i < Cc * KSc * OUTc; i += blockDim.x)
        Wsh[i] = W[i];
    __syncthreads();

    int tid = blockIdx.x * blockDim.x + threadIdx.x;
    if (tid >= Bc * Vc) return;
    int b = tid / Vc;
    int v = tid - b * Vc;

    const float* xb = x + (size_t)b * Vc * Cc;

    // center vertex features
    float xv[Cc];
    #pragma unroll
    for (int c = 0; c < Cc; c++) xv[c] = xb[(size_t)v * Cc + c];

    // adjacency row, vectorized 4x int4
    int a[NBc];
    const int4* adj4 = reinterpret_cast<const int4*>(adj + (size_t)v * NBc);
    #pragma unroll
    for (int i = 0; i < NBc / 4; i++) {
        int4 t = __ldg(&adj4[i]);
        a[i * 4 + 0] = t.x; a[i * 4 + 1] = t.y;
        a[i * 4 + 2] = t.z; a[i * 4 + 3] = t.w;
    }

    // s[k][c] = sum_n q[n,k] * nbx[n,c]
    float s[KSc][Cc];
    #pragma unroll
    for (int k = 0; k < KSc; k++)
        #pragma unroll
        for (int c = 0; c < Cc; c++) s[k][c] = 0.0f;

    int deg = 0;

    #pragma unroll
    for (int n = 0; n < NBc; n++) {
        int an = a[n];
        int valid = (an != 0);
        deg += valid;
        int ridx = valid ? (an - 1) : 0;   // safe row; contribution masked below

        const float* nr = xb + (size_t)ridx * Cc;
        float nbv[Cc], d[Cc];
        #pragma unroll
        for (int c = 0; c < Cc; c++) {
            nbv[c] = __ldg(&nr[c]);
            d[c]   = xv[c] - nbv[c];
        }

        // softmax over the 9 channels
        float m = d[0];
        #pragma unroll
        for (int c = 1; c < Cc; c++) m = fmaxf(m, d[c]);
        float e[Cc], sum = 0.0f;
        #pragma unroll
        for (int c = 0; c < Cc; c++) { e[c] = __expf(d[c] - m); sum += e[c]; }
        float inv = __fdividef(1.0f, sum);
        float msk = valid ? inv : 0.0f;    // masking: zero neighbors contribute nothing

        #pragma unroll
        for (int k = 0; k < KSc; k++) {
            float qk = e[k] * msk;
            #pragma unroll
            for (int c = 0; c < Cc; c++)
                s[k][c] = fmaf(qk, nbv[c], s[k][c]);
        }
    }

    float invdeg = (deg > 0) ? (1.0f / (float)deg) : 0.0f;

    // out[o] = relu( invdeg * sum_{k,c} s[k,c] * W[c,k,o] )
    float acc[OUTc];
    #pragma unroll
    for (int o = 0; o < OUTc; o++) acc[o] = 0.0f;

    #pragma unroll
    for (int c = 0; c < Cc; c++) {
        #pragma unroll
        for (int k = 0; k < KSc; k++) {
            float sc = s[k][c];
            const float* wrow = &Wsh[(c * KSc + k) * OUTc];
            #pragma unroll
            for (int o = 0; o < OUTc; o++)
                acc[o] = fmaf(sc, wrow[o], acc[o]);
        }
    }

    float* op = out + (size_t)tid * OUTc;
    #pragma unroll
    for (int o = 0; o < OUTc; o++)
        op[o] = fmaxf(acc[o] * invdeg, 0.0f);
}

extern "C" void kernel_launch(void* const* d_in, const int* in_sizes, int n_in,
                              void* d_out, int out_size)
{
    const float* x   = (const float*)d_in[0];   // (2, 20000, 9)
    const float* W   = (const float*)d_in[1];   // (9, 9, 16)
    const int*   adj = (const int*)d_in[2];     // (20000, 16)
    float*       out = (float*)d_out;           // (2, 20000, 16)

    const int total   = Bc * Vc;                // 40000
    const int threads = 128;
    const int blocks  = (total + threads - 1) / threads;  // 313
    nlayer_kernel<<<blocks, threads>>>(x, W, adj, out);
}